// round 16
// baseline (speedup 1.0000x reference)
#include <cuda_runtime.h>
#include <cuda_fp16.h>
#include <cstdint>

#define B_   16
#define T_   12
#define NN   1024
#define C_   64
#define NW_  10
#define K3   3072
#define BM   128
#define BN   128
#define BK   64
#define NSTG 48          // 3072/64
#define NT   512         // threads per CTA

// ---- stage smem layout (bytes): 3 stages x 32KB ----
#define SA_H 0
#define SB_H 16384
#define STG  32768
// ---- epilogue smem layout (reuses region from 0 after mainloop) ----
#define YP     132                       // Ys row stride (floats)
#define WS_OFF 67584                     // after Ys (128*132*4)
#define BS_OFF (WS_OFF + 32768)          // 100352
#define ZH_OFF (BS_OFF + 512)            // 100864
#define SMEM_DYN (ZH_OFF + 32768 + 128)  // 133760 (~130.6KB) -> 1 CTA/SM, 16 warps

// ---- scratch (device globals; allocation-free rule) ----
__device__ __half g_Ah[(size_t)K3*K3];
__device__ __half g_xh[(size_t)B_*T_*C_*NN];   // [b*T+t][c][n]
__device__ __half g_h1h[(size_t)NW_*B_*C_*K3]; // [gb][c][w]

// ---------------- helpers ----------------
__device__ __forceinline__ uint32_t smem_u32(const void* p){
    uint32_t a;
    asm("{ .reg .u64 t; cvta.to.shared.u64 t, %1; cvt.u32.u64 %0, t; }" : "=r"(a) : "l"(p));
    return a;
}
#define SWZ(o) ((o) ^ ((((uint32_t)(o))>>3)&0x70))

__device__ __forceinline__ void cp16(uint32_t d, const void* s){
    asm volatile("cp.async.cg.shared.global [%0], [%1], 16;" :: "r"(d), "l"(s));
}
#define CP_COMMIT() asm volatile("cp.async.commit_group;" ::: "memory")
#define CP_WAIT(n)  asm volatile("cp.async.wait_group %0;" :: "n"(n) : "memory")

#define LDSM4(r, a) asm volatile( \
    "ldmatrix.sync.aligned.m8n8.x4.shared.b16 {%0,%1,%2,%3}, [%4];" \
    : "=r"((r)[0]), "=r"((r)[1]), "=r"((r)[2]), "=r"((r)[3]) : "r"(a))

#define MMA(c, a, b) asm volatile( \
    "mma.sync.aligned.m16n8k16.row.col.f32.f16.f16.f32 " \
    "{%0,%1,%2,%3}, {%4,%5,%6,%7}, {%8,%9}, {%0,%1,%2,%3};" \
    : "+f"((c)[0]), "+f"((c)[1]), "+f"((c)[2]), "+f"((c)[3]) \
    : "r"((a)[0]), "r"((a)[1]), "r"((a)[2]), "r"((a)[3]), "r"((b)[0]), "r"((b)[1]))

// packed f32x2 (epilogue)
__device__ __forceinline__ unsigned long long pk2(float a, float b){
    unsigned long long r; asm("mov.b64 %0, {%1,%2};" : "=l"(r) : "f"(a), "f"(b)); return r;
}
__device__ __forceinline__ void upk2(unsigned long long v, float& a, float& b){
    asm("mov.b64 {%0,%1}, %2;" : "=f"(a), "=f"(b) : "l"(v));
}
__device__ __forceinline__ unsigned long long fma2(unsigned long long a, unsigned long long b, unsigned long long c){
    unsigned long long d; asm("fma.rn.f32x2 %0, %1, %2, %3;" : "=l"(d) : "l"(a), "l"(b), "l"(c)); return d;
}
__device__ __forceinline__ unsigned long long add2(unsigned long long a, unsigned long long b){
    unsigned long long d; asm("add.rn.f32x2 %0, %1, %2;" : "=l"(d) : "l"(a), "l"(b)); return d;
}

// ---------------- prep kernels ----------------
__global__ void k_prep_A(const float* __restrict__ A){
    size_t i = (size_t)blockIdx.x*256 + threadIdx.x;   // float4 index
    float4 v = ((const float4*)A)[i];
    __half h0 = __float2half_rn(v.x), h1 = __float2half_rn(v.y);
    __half h2 = __float2half_rn(v.z), h3 = __float2half_rn(v.w);
    ((__half2*)g_Ah)[2*i]   = __halves2half2(h0, h1);
    ((__half2*)g_Ah)[2*i+1] = __halves2half2(h2, h3);
}

// xe = x + te + se, transpose to [bt][c][n], fp16
__global__ void k_emb_t(const float* __restrict__ x,
                        const float* __restrict__ te,
                        const float* __restrict__ se){
    __shared__ float smt[64][132];
    const int nb = blockIdx.x, bt = blockIdx.y;
    const int t = bt % T_;
    const int tid = threadIdx.x;
    const int n0 = nb*128;
    const int c4 = tid & 15, rb = tid >> 4;
    float4 tv = ((const float4*)te)[t*16 + c4];
    #pragma unroll
    for (int r=0;r<8;r++){
        int row = rb + r*16;
        float4 xv = ((const float4*)x)[((size_t)bt*NN + n0+row)*16 + c4];
        float4 sv = ((const float4*)se)[(size_t)(n0+row)*16 + c4];
        smt[c4*4+0][row] = xv.x + tv.x + sv.x;
        smt[c4*4+1][row] = xv.y + tv.y + sv.y;
        smt[c4*4+2][row] = xv.z + tv.z + sv.z;
        smt[c4*4+3][row] = xv.w + tv.w + sv.w;
    }
    __syncthreads();
    const int c = tid >> 2, ns = (tid & 3)*32;
    size_t base = ((size_t)bt*C_ + c)*NN + n0 + ns;
    #pragma unroll
    for (int k=0;k<32;k+=2){
        __half ha = __float2half_rn(smt[c][ns+k]);
        __half hb = __float2half_rn(smt[c][ns+k+1]);
        *((__half2*)(g_xh + base + k)) = __halves2half2(ha, hb);
    }
}

// ---------------- main GEMM kernel (fp16, BM128xBN128, 512 thr, 4x4 warps, 3-stage) ----------------
template<int LAYER>
__global__ void __launch_bounds__(NT,1)
k_gcn(const float* __restrict__ W, const float* __restrict__ bias,
      float* __restrict__ out)
{
    extern __shared__ char smc[];
    const uint32_t sb0 = smem_u32(smc);
    const int tid  = threadIdx.x;
    const int lane = tid & 31, wid = tid >> 5;
    const int mt   = blockIdx.y;
    const int row_base = (LAYER ? NN : 0) + mt*BM;     // A-row offset
    const int pair = blockIdx.x;                       // 0..79
    const int g    = pair >> 3;
    const int b0   = (pair & 7) * 2;
    const int gb0  = g*B_ + b0;

    const int m_base = (wid & 3)*32;
    const int n_base = (wid >> 2)*32;                  // 4 n-groups of 32

    float acc[2][4][4];
    #pragma unroll
    for (int i=0;i<2;i++)
        #pragma unroll
        for (int j=0;j<4;j++)
            #pragma unroll
            for (int q=0;q<4;q++) acc[i][j][q] = 0.f;

    auto prefetch = [&](int kt, int buf){
        uint32_t s = sb0 + buf*STG;
        #pragma unroll
        for (int i=0;i<2;i++){                      // A: 128 rows x 8 chunks = 1024 cp16
            int idx = tid + i*NT;
            int row = idx >> 3, ch = idx & 7;
            size_t ga = (size_t)(row_base+row)*K3 + (size_t)kt*BK + ch*8;
            cp16(s + SA_H + SWZ(row*128 + ch*16), g_Ah + ga);
        }
        #pragma unroll
        for (int i=0;i<2;i++){                      // B: 128 n-rows (2 b x 64 c) x 8 chunks
            int idx = tid + i*NT;
            int n = idx >> 3, ch = idx & 7;
            int bl = n >> 6, c = n & 63;
            const __half *ph;
            if (LAYER==0){
                int t = g + (kt >> 4);
                ph = g_xh + (((size_t)(b0+bl)*T_ + t)*C_ + c)*NN + (size_t)(kt & 15)*BK + ch*8;
            } else {
                ph = g_h1h + ((size_t)(gb0+bl)*C_ + c)*K3 + (size_t)kt*BK + ch*8;
            }
            cp16(s + SB_H + SWZ(n*128 + ch*16), ph);
        }
    };

    // 3-stage prologue
    prefetch(0, 0); CP_COMMIT();
    prefetch(1, 1); CP_COMMIT();

    int cur = 0, nx2 = 2;                   // nx2 = (cur+2)%3
    for (int kt=0; kt<NSTG; kt++){
        if (kt+1 < NSTG){ CP_WAIT(1); } else { CP_WAIT(0); }
        __syncthreads();
        // WAR-safe: all warps passed the barrier, so stage kt-1's reads of
        // buffer (kt+2)%3 == (kt-1)%3 are complete before this prefetch
        if (kt+2 < NSTG){
            prefetch(kt+2, nx2);
            CP_COMMIT();
        }

        uint32_t s = sb0 + cur*STG;
        #pragma unroll
        for (int ks=0; ks<4; ks++){
            uint32_t aH[2][4], bH[4][2];
            #pragma unroll
            for (int i=0;i<2;i++){
                int row = m_base + i*16 + (lane & 7) + ((lane >> 3) & 1)*8;
                uint32_t kb = ks*32 + (lane >> 4)*16;
                LDSM4(aH[i], s + SA_H + SWZ(row*128 + kb));
            }
            #pragma unroll
            for (int j2=0; j2<2; j2++){
                int nr = n_base + j2*16 + (lane & 7) + (lane >> 4)*8;
                uint32_t kb = ks*32 + ((lane >> 3) & 1)*16;
                uint32_t r[4];
                LDSM4(r, s + SB_H + SWZ(nr*128 + kb));
                bH[2*j2][0]=r[0]; bH[2*j2][1]=r[1]; bH[2*j2+1][0]=r[2]; bH[2*j2+1][1]=r[3];
            }
            #pragma unroll
            for (int i=0;i<2;i++)
                #pragma unroll
                for (int j=0;j<4;j++)
                    MMA(acc[i][j], aH[i], bH[j]);
        }
        cur = (cur==2) ? 0 : cur+1;
        nx2 = (nx2==2) ? 0 : nx2+1;
    }
    __syncthreads();                        // protect stage region before epilogue reuse

    // ---- epilogue phase A: acc -> Ys fp32 [128][YP] ----
    float* Ys = (float*)smc;
    #pragma unroll
    for (int i=0;i<2;i++)
        #pragma unroll
        for (int j=0;j<4;j++){
            int r0 = m_base + i*16 + (lane >> 2);
            int c0 = n_base + j*8 + (lane & 3)*2;
            Ys[r0*YP + c0]     = acc[i][j][0];
            Ys[r0*YP + c0+1]   = acc[i][j][1];
            Ys[(r0+8)*YP + c0]   = acc[i][j][2];
            Ys[(r0+8)*YP + c0+1] = acc[i][j][3];
        }
    __syncthreads();

    // load W+bias (separate smem region) while reading y into regs
    {
        const float4* Wg = (const float4*)(W + (size_t)(g*2 + LAYER)*128*C_);
        float4* Ws4 = (float4*)(smc + WS_OFF);
        #pragma unroll
        for (int i=0;i<4;i++) Ws4[tid + i*NT] = Wg[tid + i*NT];
        if (tid < 128) ((float*)(smc + BS_OFF))[tid] = bias[(g*2 + LAYER)*128 + tid];
    }
    const int bl = tid >> 8;               // which b-block of 64 cols
    const int oh = ((tid >> 7) & 1) * 32;  // o-half handled by this thread
    const int m  = tid & 127;
    unsigned long long y2[32];
    #pragma unroll
    for (int i=0;i<32;i++)
        y2[i] = pk2(Ys[m*YP + bl*64 + 2*i], Ys[m*YP + bl*64 + 2*i + 1]);
    __syncthreads();

    const float* Ws  = (const float*)(smc + WS_OFF);
    const float* bsm = (const float*)(smc + BS_OFF);
    __half* zsH = (__half*)(smc + ZH_OFF);

    const int v  = row_base + m;                  // A row (h1 w-index for layer0)
    const int b  = b0 + bl;
    const bool mid = (LAYER==0) && (v >= NN) && (v < 2*NN);
    float* orow = out + (((size_t)b*NW_ + g)*NN + ((v - NN) & (NN-1)))*C_;

    #pragma unroll 2
    for (int oo=0;oo<32;oo++){
        const int o = oh + oo;
        const ulonglong2* w0 = (const ulonglong2*)&Ws[o*64];
        const ulonglong2* w1 = (const ulonglong2*)&Ws[(o+64)*64];
        unsigned long long p0=0,p1=0,p2=0,p3=0,q0=0,q1=0,q2=0,q3=0;
        #pragma unroll
        for (int i=0;i<8;i++){
            ulonglong2 wa = w0[2*i], wb = w0[2*i+1];
            p0 = fma2(y2[4*i+0], wa.x, p0);
            p1 = fma2(y2[4*i+1], wa.y, p1);
            p2 = fma2(y2[4*i+2], wb.x, p2);
            p3 = fma2(y2[4*i+3], wb.y, p3);
            ulonglong2 wc = w1[2*i], wd = w1[2*i+1];
            q0 = fma2(y2[4*i+0], wc.x, q0);
            q1 = fma2(y2[4*i+1], wc.y, q1);
            q2 = fma2(y2[4*i+2], wd.x, q2);
            q3 = fma2(y2[4*i+3], wd.y, q3);
        }
        unsigned long long ps = add2(add2(p0,p1), add2(p2,p3));
        unsigned long long qs = add2(add2(q0,q1), add2(q2,q3));
        float pa,pb,qa,qb;
        upk2(ps,pa,pb); upk2(qs,qa,qb);
        float zl = pa + pb + bsm[o];
        float zr = qa + qb + bsm[o+64];
        float val = zl / (1.0f + __expf(-zr));
        if (LAYER==0){
            zsH[(bl*64 + o)*128 + m] = __float2half_rn(val);
            if (mid) orow[o] = val;
        } else {
            orow[o] = fmaxf(orow[o], val);
        }
    }

    if (LAYER==0){
        __syncthreads();
        // cooperative coalesced store of h1 (C-major)
        #pragma unroll
        for (int it=0; it<16; it++){
            int ii = tid + it*NT;                  // 8192 uint32
            int m2 = ii & 63;
            int c  = (ii >> 6) & 63;
            int b2 = ii >> 12;
            size_t dst = ((size_t)(gb0+b2)*C_ + c)*K3 + row_base + m2*2;
            uint32_t vh = ((const uint32_t*)(zsH + (b2*64 + c)*128))[m2];
            *((uint32_t*)(g_h1h + dst)) = vh;
        }
    }
}

// ---------------- launch ----------------
extern "C" void kernel_launch(void* const* d_in, const int* in_sizes, int n_in,
                              void* d_out, int out_size)
{
    const float* x    = (const float*)d_in[0];
    const float* A    = (const float*)d_in[1];
    const float* W    = (const float*)d_in[2];
    const float* bias = (const float*)d_in[3];
    const float* te   = (const float*)d_in[4];
    const float* se   = (const float*)d_in[5];
    float* out = (float*)d_out;

    cudaFuncSetAttribute(k_gcn<0>, cudaFuncAttributeMaxDynamicSharedMemorySize, SMEM_DYN);
    cudaFuncSetAttribute(k_gcn<1>, cudaFuncAttributeMaxDynamicSharedMemorySize, SMEM_DYN);

    k_prep_A<<<(K3*K3/4)/256, 256>>>(A);
    k_emb_t<<<dim3(8, B_*T_), 256>>>(x, te, se);

    dim3 g0(80, K3/BM);   // x = (g, b-pair), y = m-tile
    k_gcn<0><<<g0, NT, SMEM_DYN>>>(W, bias, out);

    dim3 g1(80, NN/BM);
    k_gcn<1><<<g1, NT, SMEM_DYN>>>(W, bias, out);
}

// round 17
// speedup vs baseline: 1.2029x; 1.2029x over previous
#include <cuda_runtime.h>
#include <cuda_fp16.h>
#include <cstdint>

#define B_   16
#define T_   12
#define NN   1024
#define C_   64
#define NW_  10
#define K3   3072
#define BM   128
#define BN   64
#define BK   64
#define NSTG 48          // 3072/64

// ---- stage smem layout (bytes): 3 stages x 24KB ----
#define SA_H 0
#define SB_H 16384
#define STG  24576
// ---- epilogue smem layout (reuses stage region after mainloop) ----
#define YP     68                        // Ys row stride (floats)
#define WS_OFF 34816                     // after Ys (128*68*4)
#define BS_OFF (WS_OFF + 32768)          // 67584
#define ZH_OFF (BS_OFF + 512)            // 68096
#define SMEM_DYN (ZH_OFF + 16384 + 256)  // 84736 (~82.8KB) -> 2 CTAs/SM

// ---- scratch (device globals; allocation-free rule) ----
__device__ __half g_Ah[(size_t)K3*K3];
__device__ __half g_xh[(size_t)B_*T_*C_*NN];   // [b*T+t][c][n]
__device__ __half g_h1h[(size_t)NW_*B_*C_*K3]; // [gb][c][w]

// ---------------- helpers ----------------
__device__ __forceinline__ uint32_t smem_u32(const void* p){
    uint32_t a;
    asm("{ .reg .u64 t; cvta.to.shared.u64 t, %1; cvt.u32.u64 %0, t; }" : "=r"(a) : "l"(p));
    return a;
}
#define SWZ(o) ((o) ^ ((((uint32_t)(o))>>3)&0x70))

__device__ __forceinline__ void cp16(uint32_t d, const void* s){
    asm volatile("cp.async.cg.shared.global [%0], [%1], 16;" :: "r"(d), "l"(s));
}
#define CP_COMMIT() asm volatile("cp.async.commit_group;" ::: "memory")
#define CP_WAIT(n)  asm volatile("cp.async.wait_group %0;" :: "n"(n) : "memory")

#define LDSM4(r, a) asm volatile( \
    "ldmatrix.sync.aligned.m8n8.x4.shared.b16 {%0,%1,%2,%3}, [%4];" \
    : "=r"((r)[0]), "=r"((r)[1]), "=r"((r)[2]), "=r"((r)[3]) : "r"(a))

#define MMA(c, a, b) asm volatile( \
    "mma.sync.aligned.m16n8k16.row.col.f32.f16.f16.f32 " \
    "{%0,%1,%2,%3}, {%4,%5,%6,%7}, {%8,%9}, {%0,%1,%2,%3};" \
    : "+f"((c)[0]), "+f"((c)[1]), "+f"((c)[2]), "+f"((c)[3]) \
    : "r"((a)[0]), "r"((a)[1]), "r"((a)[2]), "r"((a)[3]), "r"((b)[0]), "r"((b)[1]))

// packed f32x2 (epilogue)
__device__ __forceinline__ unsigned long long pk2(float a, float b){
    unsigned long long r; asm("mov.b64 %0, {%1,%2};" : "=l"(r) : "f"(a), "f"(b)); return r;
}
__device__ __forceinline__ void upk2(unsigned long long v, float& a, float& b){
    asm("mov.b64 {%0,%1}, %2;" : "=f"(a), "=f"(b) : "l"(v));
}
__device__ __forceinline__ unsigned long long fma2(unsigned long long a, unsigned long long b, unsigned long long c){
    unsigned long long d; asm("fma.rn.f32x2 %0, %1, %2, %3;" : "=l"(d) : "l"(a), "l"(b), "l"(c)); return d;
}
__device__ __forceinline__ unsigned long long add2(unsigned long long a, unsigned long long b){
    unsigned long long d; asm("add.rn.f32x2 %0, %1, %2;" : "=l"(d) : "l"(a), "l"(b)); return d;
}

// ---------------- prep kernels ----------------
__global__ void k_prep_A(const float* __restrict__ A){
    size_t i = (size_t)blockIdx.x*256 + threadIdx.x;   // float4 index
    float4 v = ((const float4*)A)[i];
    __half h0 = __float2half_rn(v.x), h1 = __float2half_rn(v.y);
    __half h2 = __float2half_rn(v.z), h3 = __float2half_rn(v.w);
    ((__half2*)g_Ah)[2*i]   = __halves2half2(h0, h1);
    ((__half2*)g_Ah)[2*i+1] = __halves2half2(h2, h3);
}

// xe = x + te + se, transpose to [bt][c][n], fp16
__global__ void k_emb_t(const float* __restrict__ x,
                        const float* __restrict__ te,
                        const float* __restrict__ se){
    __shared__ float smt[64][132];
    const int nb = blockIdx.x, bt = blockIdx.y;
    const int t = bt % T_;
    const int tid = threadIdx.x;
    const int n0 = nb*128;
    const int c4 = tid & 15, rb = tid >> 4;
    float4 tv = ((const float4*)te)[t*16 + c4];
    #pragma unroll
    for (int r=0;r<8;r++){
        int row = rb + r*16;
        float4 xv = ((const float4*)x)[((size_t)bt*NN + n0+row)*16 + c4];
        float4 sv = ((const float4*)se)[(size_t)(n0+row)*16 + c4];
        smt[c4*4+0][row] = xv.x + tv.x + sv.x;
        smt[c4*4+1][row] = xv.y + tv.y + sv.y;
        smt[c4*4+2][row] = xv.z + tv.z + sv.z;
        smt[c4*4+3][row] = xv.w + tv.w + sv.w;
    }
    __syncthreads();
    const int c = tid >> 2, ns = (tid & 3)*32;
    size_t base = ((size_t)bt*C_ + c)*NN + n0 + ns;
    #pragma unroll
    for (int k=0;k<32;k+=2){
        __half ha = __float2half_rn(smt[c][ns+k]);
        __half hb = __float2half_rn(smt[c][ns+k+1]);
        *((__half2*)(g_xh + base + k)) = __halves2half2(ha, hb);
    }
}

// ---------------- main GEMM kernel (fp16, split-K warps 2m x 2n x 2k, 2 CTAs/SM) ----------------
template<int LAYER>
__global__ void __launch_bounds__(256,2)
k_gcn(const float* __restrict__ W, const float* __restrict__ bias,
      float* __restrict__ out)
{
    extern __shared__ char smc[];
    const uint32_t sb0 = smem_u32(smc);
    const int tid  = threadIdx.x;
    const int lane = tid & 31, wid = tid >> 5;
    const int mt   = blockIdx.y;
    const int row_base = (LAYER ? NN : 0) + mt*BM;     // A-row offset
    const int pair = blockIdx.x;                       // 0..159 = g*16 + b
    const int g    = pair >> 4;
    const int b    = pair & 15;
    const int gb   = g*B_ + b;

    const int m_base = (wid & 1)*64;        // warp tile 64 m-rows
    const int n_base = ((wid >> 1) & 1)*32; // warp tile 32 n-cols
    const int wk2    = (wid >> 2)*2;        // k-half: ks offset 0 or 2

    float acc[4][4][4];
    #pragma unroll
    for (int i=0;i<4;i++)
        #pragma unroll
        for (int j=0;j<4;j++)
            #pragma unroll
            for (int q=0;q<4;q++) acc[i][j][q] = 0.f;

    auto prefetch = [&](int kt, int buf){
        uint32_t s = sb0 + buf*STG;
        #pragma unroll
        for (int i=0;i<4;i++){                      // A: 128 rows x 8 chunks
            int idx = tid + i*256;
            int row = idx >> 3, ch = idx & 7;
            size_t ga = (size_t)(row_base+row)*K3 + (size_t)kt*BK + ch*8;
            cp16(s + SA_H + SWZ(row*128 + ch*16), g_Ah + ga);
        }
        #pragma unroll
        for (int i=0;i<2;i++){                      // B: 64 n-rows x 8 chunks
            int idx = tid + i*256;
            int c = idx >> 3, ch = idx & 7;
            const __half *ph;
            if (LAYER==0){
                int t = g + (kt >> 4);
                ph = g_xh + (((size_t)b*T_ + t)*C_ + c)*NN + (size_t)(kt & 15)*BK + ch*8;
            } else {
                ph = g_h1h + ((size_t)gb*C_ + c)*K3 + (size_t)kt*BK + ch*8;
            }
            cp16(s + SB_H + SWZ(c*128 + ch*16), ph);
        }
    };

    // 3-stage prologue
    prefetch(0, 0); CP_COMMIT();
    prefetch(1, 1); CP_COMMIT();

    int cur = 0, nx2 = 2;                   // nx2 = (cur+2)%3
    for (int kt=0; kt<NSTG; kt++){
        if (kt+1 < NSTG){ CP_WAIT(1); } else { CP_WAIT(0); }
        __syncthreads();
        // WAR-safe: all warps passed the barrier, so stage kt-1's reads of
        // buffer (kt+2)%3 == (kt-1)%3 are complete before this prefetch
        if (kt+2 < NSTG){
            prefetch(kt+2, nx2);
            CP_COMMIT();
        }

        uint32_t s = sb0 + cur*STG;
        #pragma unroll
        for (int ksl=0; ksl<2; ksl++){
            const int ks = wk2 + ksl;
            uint32_t aH[4][4], bH[4][2];
            #pragma unroll
            for (int i=0;i<4;i++){
                int row = m_base + i*16 + (lane & 7) + ((lane >> 3) & 1)*8;
                uint32_t kb = ks*32 + (lane >> 4)*16;
                LDSM4(aH[i], s + SA_H + SWZ(row*128 + kb));
            }
            #pragma unroll
            for (int j2=0; j2<2; j2++){
                int nr = n_base + j2*16 + (lane & 7) + (lane >> 4)*8;
                uint32_t kb = ks*32 + ((lane >> 3) & 1)*16;
                uint32_t r[4];
                LDSM4(r, s + SB_H + SWZ(nr*128 + kb));
                bH[2*j2][0]=r[0]; bH[2*j2][1]=r[1]; bH[2*j2+1][0]=r[2]; bH[2*j2+1][1]=r[3];
            }
            #pragma unroll
            for (int i=0;i<4;i++)
                #pragma unroll
                for (int j=0;j<4;j++)
                    MMA(acc[i][j], aH[i], bH[j]);
        }
        cur = (cur==2) ? 0 : cur+1;
        nx2 = (nx2==2) ? 0 : nx2+1;
    }
    __syncthreads();                        // protect stage region before epilogue reuse

    // ---- epilogue phase A: k-reduction into Ys fp32 [128][YP] ----
    float* Ys = (float*)smc;
    if (wk2 == 0){                          // k-half 0 warps write
        #pragma unroll
        for (int i=0;i<4;i++)
            #pragma unroll
            for (int j=0;j<4;j++){
                int r0 = m_base + i*16 + (lane >> 2);
                int c0 = n_base + j*8 + (lane & 3)*2;
                Ys[r0*YP + c0]       = acc[i][j][0];
                Ys[r0*YP + c0+1]     = acc[i][j][1];
                Ys[(r0+8)*YP + c0]   = acc[i][j][2];
                Ys[(r0+8)*YP + c0+1] = acc[i][j][3];
            }
    }
    __syncthreads();
    if (wk2 != 0){                          // k-half 1 warps accumulate
        #pragma unroll
        for (int i=0;i<4;i++)
            #pragma unroll
            for (int j=0;j<4;j++){
                int r0 = m_base + i*16 + (lane >> 2);
                int c0 = n_base + j*8 + (lane & 3)*2;
                Ys[r0*YP + c0]       += acc[i][j][0];
                Ys[r0*YP + c0+1]     += acc[i][j][1];
                Ys[(r0+8)*YP + c0]   += acc[i][j][2];
                Ys[(r0+8)*YP + c0+1] += acc[i][j][3];
            }
    }
    __syncthreads();

    // load W+bias (separate smem region) while reading y into regs
    {
        const float4* Wg = (const float4*)(W + (size_t)(g*2 + LAYER)*128*C_);
        float4* Ws4 = (float4*)(smc + WS_OFF);
        #pragma unroll
        for (int i=0;i<8;i++) Ws4[tid + i*256] = Wg[tid + i*256];
        if (tid < 128) ((float*)(smc + BS_OFF))[tid] = bias[(g*2 + LAYER)*128 + tid];
    }
    const int m  = tid & 127;
    const int oh = (tid >> 7) * 32;      // thread pair splits the 64 o-outputs
    unsigned long long y2[32];
    #pragma unroll
    for (int i=0;i<32;i++)
        y2[i] = pk2(Ys[m*YP + 2*i], Ys[m*YP + 2*i + 1]);
    __syncthreads();

    const float* Ws  = (const float*)(smc + WS_OFF);
    const float* bsm = (const float*)(smc + BS_OFF);
    __half* zsH = (__half*)(smc + ZH_OFF);

    const int v  = row_base + m;                  // A row (h1 w-index for layer0)
    const bool mid = (LAYER==0) && (v >= NN) && (v < 2*NN);
    float* orow = out + (((size_t)b*NW_ + g)*NN + ((v - NN) & (NN-1)))*C_;

    #pragma unroll 2
    for (int oo=0;oo<32;oo++){
        const int o = oh + oo;
        const ulonglong2* w0 = (const ulonglong2*)&Ws[o*64];
        const ulonglong2* w1 = (const ulonglong2*)&Ws[(o+64)*64];
        unsigned long long p0=0,p1=0,p2=0,p3=0,q0=0,q1=0,q2=0,q3=0;
        #pragma unroll
        for (int i=0;i<8;i++){
            ulonglong2 wa = w0[2*i], wb = w0[2*i+1];
            p0 = fma2(y2[4*i+0], wa.x, p0);
            p1 = fma2(y2[4*i+1], wa.y, p1);
            p2 = fma2(y2[4*i+2], wb.x, p2);
            p3 = fma2(y2[4*i+3], wb.y, p3);
            ulonglong2 wc = w1[2*i], wd = w1[2*i+1];
            q0 = fma2(y2[4*i+0], wc.x, q0);
            q1 = fma2(y2[4*i+1], wc.y, q1);
            q2 = fma2(y2[4*i+2], wd.x, q2);
            q3 = fma2(y2[4*i+3], wd.y, q3);
        }
        unsigned long long ps = add2(add2(p0,p1), add2(p2,p3));
        unsigned long long qs = add2(add2(q0,q1), add2(q2,q3));
        float pa,pb,qa,qb;
        upk2(ps,pa,pb); upk2(qs,qa,qb);
        float zl = pa + pb + bsm[o];
        float zr = qa + qb + bsm[o+64];
        float val = zl / (1.0f + __expf(-zr));
        if (LAYER==0){
            zsH[o*128 + m] = __float2half_rn(val);
            if (mid) orow[o] = val;
        } else {
            orow[o] = fmaxf(orow[o], val);
        }
    }

    if (LAYER==0){
        __syncthreads();
        // cooperative coalesced store of h1 (C-major)
        #pragma unroll
        for (int it=0; it<16; it++){
            int ii = tid + it*256;                 // 4096 uint32
            int m2 = ii & 63;
            int c  = ii >> 6;
            size_t dst = ((size_t)gb*C_ + c)*K3 + row_base + m2*2;
            uint32_t vh = ((const uint32_t*)(zsH + c*128))[m2];
            *((uint32_t*)(g_h1h + dst)) = vh;
        }
    }
}

// ---------------- launch ----------------
extern "C" void kernel_launch(void* const* d_in, const int* in_sizes, int n_in,
                              void* d_out, int out_size)
{
    const float* x    = (const float*)d_in[0];
    const float* A    = (const float*)d_in[1];
    const float* W    = (const float*)d_in[2];
    const float* bias = (const float*)d_in[3];
    const float* te   = (const float*)d_in[4];
    const float* se   = (const float*)d_in[5];
    float* out = (float*)d_out;

    cudaFuncSetAttribute(k_gcn<0>, cudaFuncAttributeMaxDynamicSharedMemorySize, SMEM_DYN);
    cudaFuncSetAttribute(k_gcn<1>, cudaFuncAttributeMaxDynamicSharedMemorySize, SMEM_DYN);

    k_prep_A<<<(K3*K3/4)/256, 256>>>(A);
    k_emb_t<<<dim3(8, B_*T_), 256>>>(x, te, se);

    dim3 g0(160, K3/BM);   // x = (g,b), y = m-tile
    k_gcn<0><<<g0, 256, SMEM_DYN>>>(W, bias, out);

    dim3 g1(160, NN/BM);
    k_gcn<1><<<g1, 256, SMEM_DYN>>>(W, bias, out);
}